// round 1
// baseline (speedup 1.0000x reference)
#include <cuda_runtime.h>
#include <math.h>

#define T_TOK    4096
#define DM       1024      // d_model
#define DH       4096      // d_hidden
#define NE       8
#define NASSIGN  (T_TOK * 2)

// ---------------- static device scratch (no allocations allowed) ----------------
__device__ float g_H[(size_t)NASSIGN * DH];   // gathered hidden activations [8192, 4096]
__device__ int   g_tok[NASSIGN];              // token id per assignment slot (compact per expert)
__device__ float g_wgt[NASSIGN];              // combine weight per assignment slot
__device__ int   g_eid[NASSIGN];              // per-token chosen experts (2 per token)
__device__ float g_ew [NASSIGN];              // per-token weights (2 per token)
__device__ int   g_cnt[NE];
__device__ int   g_off[NE];
__device__ int   g_cur[NE];

// ---------------- init / zero ----------------
__global__ void k_init() {
    if (threadIdx.x < NE) g_cnt[threadIdx.x] = 0;
}

__global__ void k_zero_out(float* __restrict__ out) {
    size_t i = (size_t)blockIdx.x * blockDim.x + threadIdx.x;
    if (i < (size_t)T_TOK * DM / 4) {
        float4 z = make_float4(0.f, 0.f, 0.f, 0.f);
        reinterpret_cast<float4*>(out)[i] = z;
    }
}

// ---------------- gating: logits, top-2, softmax ----------------
// one warp per token; 8 warps per block
__global__ void k_gate(const float* __restrict__ x, const float* __restrict__ Wg,
                       const float* __restrict__ bg, float* __restrict__ out_logits) {
    int warp = threadIdx.x >> 5, lane = threadIdx.x & 31;
    int t = blockIdx.x * 8 + warp;
    if (t >= T_TOK) return;

    const float* xr = x + (size_t)t * DM;
    float acc[NE];
#pragma unroll
    for (int e = 0; e < NE; e++) acc[e] = 0.f;

    for (int k = lane; k < DM; k += 32) {
        float xv = xr[k];
        const float* w = Wg + (size_t)k * NE;
#pragma unroll
        for (int e = 0; e < NE; e++) acc[e] += xv * w[e];
    }
#pragma unroll
    for (int e = 0; e < NE; e++)
#pragma unroll
        for (int o = 16; o; o >>= 1) acc[e] += __shfl_xor_sync(0xffffffffu, acc[e], o);

    if (lane == 0) {
#pragma unroll
        for (int e = 0; e < NE; e++) {
            acc[e] += bg[e];
            out_logits[(size_t)t * NE + e] = acc[e];
        }
        // top-2 (lowest index wins ties, matching jax.lax.top_k)
        int b0 = 0;
#pragma unroll
        for (int e = 1; e < NE; e++) if (acc[e] > acc[b0]) b0 = e;
        int b1 = (b0 == 0) ? 1 : 0;
#pragma unroll
        for (int e = 0; e < NE; e++) if (e != b0 && acc[e] > acc[b1]) b1 = e;

        float ex = expf(acc[b1] - acc[b0]);   // <= 1
        float w0 = 1.f / (1.f + ex);
        float w1 = ex * w0;

        g_eid[2 * t]     = b0;  g_ew[2 * t]     = w0;
        g_eid[2 * t + 1] = b1;  g_ew[2 * t + 1] = w1;
        atomicAdd(&g_cnt[b0], 1);
        atomicAdd(&g_cnt[b1], 1);
    }
}

__global__ void k_offsets() {
    if (threadIdx.x == 0) {
        int s = 0;
#pragma unroll
        for (int e = 0; e < NE; e++) { g_off[e] = s; g_cur[e] = s; s += g_cnt[e]; }
    }
}

__global__ void k_scatter() {
    int a = blockIdx.x * blockDim.x + threadIdx.x;
    if (a < NASSIGN) {
        int e = g_eid[a];
        int pos = atomicAdd(&g_cur[e], 1);
        g_tok[pos] = a >> 1;
        g_wgt[pos] = g_ew[a];
    }
}

// ---------------- GEMM1: H[slot, :] = relu(x[tok] @ W1[e] + b1[e]) ----------------
// 128x128 tile, BK=8, 256 threads, 8x8 per thread
__global__ void __launch_bounds__(256, 2)
k_gemm1(const float* __restrict__ x, const float* __restrict__ W1,
        const float* __restrict__ b1) {
    const int e   = blockIdx.z;
    const int cnt = g_cnt[e];
    const int m0  = blockIdx.y * 128;
    if (m0 >= cnt) return;
    const int off = g_off[e];
    const int n0  = blockIdx.x * 128;
    const float* W = W1 + (size_t)e * DM * DH;

    __shared__ float As[8][128];
    __shared__ float Bs[8][128];

    const int tid  = threadIdx.x;
    const int aRow = tid >> 1;          // 0..127
    const int aK   = (tid & 1) * 4;     // 0 or 4
    const int bRow = tid >> 5;          // 0..7
    const int bCol = (tid & 31) * 4;    // 0..124
    const int rc   = (tid >> 4) * 8;    // acc row base
    const int cc   = (tid & 15) * 8;    // acc col base

    const int gRow = m0 + aRow;
    const float* arow = nullptr;
    if (gRow < cnt) arow = x + (size_t)g_tok[off + gRow] * DM;

    float acc[8][8];
#pragma unroll
    for (int i = 0; i < 8; i++)
#pragma unroll
        for (int j = 0; j < 8; j++) acc[i][j] = 0.f;

    for (int k0 = 0; k0 < DM; k0 += 8) {
        float4 av = make_float4(0.f, 0.f, 0.f, 0.f);
        if (arow) av = *reinterpret_cast<const float4*>(arow + k0 + aK);
        float4 bv = *reinterpret_cast<const float4*>(W + (size_t)(k0 + bRow) * DH + n0 + bCol);

        __syncthreads();
        As[aK + 0][aRow] = av.x;
        As[aK + 1][aRow] = av.y;
        As[aK + 2][aRow] = av.z;
        As[aK + 3][aRow] = av.w;
        *reinterpret_cast<float4*>(&Bs[bRow][bCol]) = bv;
        __syncthreads();

#pragma unroll
        for (int kk = 0; kk < 8; kk++) {
            float a[8], b[8];
            *reinterpret_cast<float4*>(a)     = *reinterpret_cast<const float4*>(&As[kk][rc]);
            *reinterpret_cast<float4*>(a + 4) = *reinterpret_cast<const float4*>(&As[kk][rc + 4]);
            *reinterpret_cast<float4*>(b)     = *reinterpret_cast<const float4*>(&Bs[kk][cc]);
            *reinterpret_cast<float4*>(b + 4) = *reinterpret_cast<const float4*>(&Bs[kk][cc + 4]);
#pragma unroll
            for (int i = 0; i < 8; i++)
#pragma unroll
                for (int j = 0; j < 8; j++) acc[i][j] += a[i] * b[j];
        }
    }

    float bias[8];
#pragma unroll
    for (int j = 0; j < 8; j++) bias[j] = b1[(size_t)e * DH + n0 + cc + j];

#pragma unroll
    for (int i = 0; i < 8; i++) {
        int gi = m0 + rc + i;
        if (gi < cnt) {
            float* hrow = g_H + (size_t)(off + gi) * DH + n0 + cc;
#pragma unroll
            for (int j = 0; j < 8; j++) {
                float v = acc[i][j] + bias[j];
                hrow[j] = v > 0.f ? v : 0.f;
            }
        }
    }
}

// ---------------- GEMM2: out[tok] += w * (H[slot] @ W2[e] + b2[e]) ----------------
__global__ void __launch_bounds__(256, 2)
k_gemm2(const float* __restrict__ W2, const float* __restrict__ b2,
        float* __restrict__ out) {
    const int e   = blockIdx.z;
    const int cnt = g_cnt[e];
    const int m0  = blockIdx.y * 128;
    if (m0 >= cnt) return;
    const int off = g_off[e];
    const int n0  = blockIdx.x * 128;
    const float* W = W2 + (size_t)e * DH * DM;

    __shared__ float As[8][128];
    __shared__ float Bs[8][128];

    const int tid  = threadIdx.x;
    const int aRow = tid >> 1;
    const int aK   = (tid & 1) * 4;
    const int bRow = tid >> 5;
    const int bCol = (tid & 31) * 4;
    const int rc   = (tid >> 4) * 8;
    const int cc   = (tid & 15) * 8;

    const int gRow = m0 + aRow;
    const float* arow = nullptr;
    if (gRow < cnt) arow = g_H + (size_t)(off + gRow) * DH;

    float acc[8][8];
#pragma unroll
    for (int i = 0; i < 8; i++)
#pragma unroll
        for (int j = 0; j < 8; j++) acc[i][j] = 0.f;

    for (int k0 = 0; k0 < DH; k0 += 8) {
        float4 av = make_float4(0.f, 0.f, 0.f, 0.f);
        if (arow) av = *reinterpret_cast<const float4*>(arow + k0 + aK);
        float4 bv = *reinterpret_cast<const float4*>(W + (size_t)(k0 + bRow) * DM + n0 + bCol);

        __syncthreads();
        As[aK + 0][aRow] = av.x;
        As[aK + 1][aRow] = av.y;
        As[aK + 2][aRow] = av.z;
        As[aK + 3][aRow] = av.w;
        *reinterpret_cast<float4*>(&Bs[bRow][bCol]) = bv;
        __syncthreads();

#pragma unroll
        for (int kk = 0; kk < 8; kk++) {
            float a[8], b[8];
            *reinterpret_cast<float4*>(a)     = *reinterpret_cast<const float4*>(&As[kk][rc]);
            *reinterpret_cast<float4*>(a + 4) = *reinterpret_cast<const float4*>(&As[kk][rc + 4]);
            *reinterpret_cast<float4*>(b)     = *reinterpret_cast<const float4*>(&Bs[kk][cc]);
            *reinterpret_cast<float4*>(b + 4) = *reinterpret_cast<const float4*>(&Bs[kk][cc + 4]);
#pragma unroll
            for (int i = 0; i < 8; i++)
#pragma unroll
                for (int j = 0; j < 8; j++) acc[i][j] += a[i] * b[j];
        }
    }

    float bias[8];
#pragma unroll
    for (int j = 0; j < 8; j++) bias[j] = b2[(size_t)e * DM + n0 + cc + j];

#pragma unroll
    for (int i = 0; i < 8; i++) {
        int gi = m0 + rc + i;
        if (gi < cnt) {
            int   tok = g_tok[off + gi];
            float w   = g_wgt[off + gi];
            float* orow = out + (size_t)tok * DM + n0 + cc;
#pragma unroll
            for (int j = 0; j < 8; j++) {
                atomicAdd(&orow[j], w * (acc[i][j] + bias[j]));
            }
        }
    }
}

// ---------------- launch ----------------
extern "C" void kernel_launch(void* const* d_in, const int* in_sizes, int n_in,
                              void* d_out, int out_size) {
    const float* x  = (const float*)d_in[0];
    const float* Wg = (const float*)d_in[1];
    const float* bg = (const float*)d_in[2];
    const float* W1 = (const float*)d_in[3];
    const float* b1 = (const float*)d_in[4];
    const float* W2 = (const float*)d_in[5];
    const float* b2 = (const float*)d_in[6];
    float* out = (float*)d_out;

    k_init<<<1, 32>>>();
    k_zero_out<<<(T_TOK * DM / 4 + 255) / 256, 256>>>(out);
    k_gate<<<T_TOK / 8, 256>>>(x, Wg, bg, out + (size_t)T_TOK * DM);
    k_offsets<<<1, 32>>>();
    k_scatter<<<(NASSIGN + 255) / 256, 256>>>();
    k_gemm1<<<dim3(DH / 128, T_TOK / 128, NE), 256>>>(x, W1, b1);
    k_gemm2<<<dim3(DM / 128, T_TOK / 128, NE), 256>>>(W2, b2, out);
}